// round 1
// baseline (speedup 1.0000x reference)
#include <cuda_runtime.h>

// Problem constants (fixed shapes from reference)
#define DD   16
#define HH   56
#define WW   56
#define PP   (DD*HH*WW)      // 50176 output (and input) spatial positions
#define CIN  32
#define COUT 64
#define KK   27              // 3x3x3
#define COFF 81              // 3*K offset channels
#define DHW  PP
#define OWPAD 84             // 81 padded to multiple of 4 for float4

// Scratch (static device allocations are allowed; cudaMalloc is not)
__device__ float g_off[COFF * PP];          // offsets [c][p], c = k*3 + comp
__device__ float g_wr [KK * CIN * COUT];    // main weight rearranged [k][ci][co]
__device__ float g_owr[KK * CIN * OWPAD];   // offset weight rearranged [k][ci][c(81 pad 84)]

// ---------------------------------------------------------------------------
// Rearrange weights once per launch (tiny)
// ---------------------------------------------------------------------------
__global__ void rearrange_kernel(const float* __restrict__ offw,
                                 const float* __restrict__ w) {
    int i = blockIdx.x * blockDim.x + threadIdx.x;
    if (i < KK * CIN * OWPAD) {
        int c  = i % OWPAD;
        int t  = i / OWPAD;
        int ci = t % CIN;
        int k  = t / CIN;
        // offw layout: [c(81)][ci(32)][k(27)]
        g_owr[i] = (c < COFF) ? offw[(c * CIN + ci) * KK + k] : 0.f;
    }
    if (i < KK * CIN * COUT) {
        int co = i % COUT;
        int t  = i / COUT;
        int ci = t % CIN;
        int k  = t / CIN;
        // w layout: [co(64)][ci(32)][k(27)]
        g_wr[i] = w[(co * CIN + ci) * KK + k];
    }
}

// ---------------------------------------------------------------------------
// Stage 1: dense offset conv.  lane = output position; 81 accumulators/thread.
// ---------------------------------------------------------------------------
__global__ __launch_bounds__(128)
void offconv_kernel(const float* __restrict__ x, const float* __restrict__ ob) {
    __shared__ float ws[CIN * OWPAD];   // weights for current k: [ci][c] (10.5 KB)

    int tid   = threadIdx.x;
    int gwarp = blockIdx.x * 4 + (tid >> 5);
    int lane  = tid & 31;
    int p     = gwarp * 32 + lane;                 // 50176 = 1568 warps exactly
    int zo    = p / (HH * WW);
    int r     = p - zo * (HH * WW);
    int yo    = r / WW;
    int xo    = r - yo * WW;

    float acc[COFF];
#pragma unroll
    for (int c = 0; c < COFF; c++) acc[c] = 0.f;

    for (int k = 0; k < KK; k++) {
        __syncthreads();
        {   // stage weights for this k: 32*84 floats = 672 float4
            const float4* src = (const float4*)(g_owr + k * CIN * OWPAD);
            float4* dst = (float4*)ws;
            for (int i = tid; i < (CIN * OWPAD) / 4; i += 128) dst[i] = src[i];
        }
        __syncthreads();

        int kz = k / 9, ky = (k / 3) % 3, kx = k % 3;
        int zi = zo + kz - 1, yi = yo + ky - 1, xi = xo + kx - 1;
        bool valid = ((unsigned)zi < DD) & ((unsigned)yi < HH) & ((unsigned)xi < WW);
        int xidx = (zi * HH + yi) * WW + xi;

#pragma unroll 4
        for (int ci = 0; ci < CIN; ci++) {
            float xv = valid ? __ldg(x + ci * DHW + xidx) : 0.f;
            const float4* wv = (const float4*)(ws + ci * OWPAD);
#pragma unroll
            for (int j = 0; j < 20; j++) {
                float4 w4 = wv[j];
                acc[4*j+0] += xv * w4.x;
                acc[4*j+1] += xv * w4.y;
                acc[4*j+2] += xv * w4.z;
                acc[4*j+3] += xv * w4.w;
            }
            acc[80] += xv * ws[ci * OWPAD + 80];
        }
    }

#pragma unroll
    for (int c = 0; c < COFF; c++)
        g_off[c * PP + p] = acc[c] + __ldg(ob + c);   // coalesced over p
}

// ---------------------------------------------------------------------------
// Stage 2: trilinear deformable sampling fused with the 64xCinK GEMM.
// lane = output position; 64 accumulators/thread; weights broadcast from smem.
// ---------------------------------------------------------------------------
__global__ __launch_bounds__(128)
void deform_kernel(const float* __restrict__ x, const float* __restrict__ bias,
                   float* __restrict__ out) {
    __shared__ float ws[CIN * COUT];    // weights for current k: [ci][co] (8 KB)

    int tid   = threadIdx.x;
    int gwarp = blockIdx.x * 4 + (tid >> 5);
    int lane  = tid & 31;
    int p     = gwarp * 32 + lane;
    int zo    = p / (HH * WW);
    int r     = p - zo * (HH * WW);
    int yo    = r / WW;
    int xo    = r - yo * WW;

    float acc[COUT];
#pragma unroll
    for (int c = 0; c < COUT; c++) acc[c] = 0.f;

    for (int k = 0; k < KK; k++) {
        __syncthreads();
        {   // stage weights for this k: 2048 floats = 512 float4
            const float4* src = (const float4*)(g_wr + k * CIN * COUT);
            float4* dst = (float4*)ws;
            for (int i = tid; i < (CIN * COUT) / 4; i += 128) dst[i] = src[i];
        }
        __syncthreads();

        int kz = k / 9, ky = (k / 3) % 3, kx = k % 3;
        float dz = g_off[(3*k+0) * PP + p];
        float dy = g_off[(3*k+1) * PP + p];
        float dx = g_off[(3*k+2) * PP + p];
        float zc = (float)(zo + kz - 1) + dz;
        float yc = (float)(yo + ky - 1) + dy;
        float xc = (float)(xo + kx - 1) + dx;
        float z0f = floorf(zc), y0f = floorf(yc), x0f = floorf(xc);
        float fz = zc - z0f, fy = yc - y0f, fx = xc - x0f;
        int z0 = (int)z0f, y0 = (int)y0f, x0 = (int)x0f;

        float w8[8];
        int   id8[8];
#pragma unroll
        for (int j = 0; j < 8; j++) {
            int dzc = (j >> 2) & 1, dyc = (j >> 1) & 1, dxc = j & 1;
            int zi = z0 + dzc, yi = y0 + dyc, xi = x0 + dxc;
            bool v = ((unsigned)zi < DD) & ((unsigned)yi < HH) & ((unsigned)xi < WW);
            float wz = dzc ? fz : 1.f - fz;
            float wy = dyc ? fy : 1.f - fy;
            float wx = dxc ? fx : 1.f - fx;
            float wt = wz * wy * wx;
            w8[j] = v ? wt : 0.f;
            int zic = min(max(zi, 0), DD - 1);
            int yic = min(max(yi, 0), HH - 1);
            int xic = min(max(xi, 0), WW - 1);
            id8[j] = (zic * HH + yic) * WW + xic;
        }

#pragma unroll 4
        for (int ci = 0; ci < CIN; ci++) {
            const float* xp = x + ci * DHW;
            float s = 0.f;
#pragma unroll
            for (int j = 0; j < 8; j++) s += w8[j] * __ldg(xp + id8[j]);
            const float4* wv = (const float4*)(ws + ci * COUT);
#pragma unroll
            for (int j = 0; j < 16; j++) {
                float4 w4 = wv[j];
                acc[4*j+0] += s * w4.x;
                acc[4*j+1] += s * w4.y;
                acc[4*j+2] += s * w4.z;
                acc[4*j+3] += s * w4.w;
            }
        }
    }

#pragma unroll
    for (int co = 0; co < COUT; co++)
        out[co * PP + p] = acc[co] + __ldg(bias + co);   // coalesced over p
}

// ---------------------------------------------------------------------------
extern "C" void kernel_launch(void* const* d_in, const int* in_sizes, int n_in,
                              void* d_out, int out_size) {
    const float* x    = (const float*)d_in[0];  // [32,16,56,56]
    const float* offw = (const float*)d_in[1];  // [81,32,3,3,3]
    const float* offb = (const float*)d_in[2];  // [81]
    const float* w    = (const float*)d_in[3];  // [64,32,3,3,3]
    const float* b    = (const float*)d_in[4];  // [64]
    float* out = (float*)d_out;                 // [64,16,56,56]

    rearrange_kernel<<<(KK * CIN * OWPAD + 255) / 256, 256>>>(offw, w);
    offconv_kernel<<<392, 128>>>(x, offb);      // 392 blocks * 4 warps * 32 = 50176
    deform_kernel<<<392, 128>>>(x, b, out);
}

// round 2
// speedup vs baseline: 1.0056x; 1.0056x over previous
#include <cuda_runtime.h>

// Problem constants (fixed shapes from reference)
#define DD   16
#define HH   56
#define WW   56
#define PP   (DD*HH*WW)      // 50176 output (and input) spatial positions
#define CIN  32
#define COUT 64
#define KK   27              // 3x3x3
#define COFF 81              // 3*K offset channels
#define DHW  PP
#define OWPAD 84             // 81 padded to multiple of 4 (16B rows, zero-padded)

// Scratch (static device arrays; cudaMalloc is forbidden)
__device__ float g_off[COFF * PP];          // offsets [c][p], c = k*3 + comp
__device__ float g_wr [KK * CIN * COUT];    // main weight rearranged [k][ci][co]
__device__ float g_owr[KK * CIN * OWPAD];   // offset weight rearranged [k][ci][c(81 pad 84)]

// ---- packed fp32x2 helpers (sm_103a: 2x fp32 FMA per issue slot) ----------
__device__ __forceinline__ unsigned long long fma2(unsigned long long a,
                                                   unsigned long long b,
                                                   unsigned long long c) {
    unsigned long long d;
    asm("fma.rn.f32x2 %0, %1, %2, %3;" : "=l"(d) : "l"(a), "l"(b), "l"(c));
    return d;
}
__device__ __forceinline__ unsigned long long pack2(float s) {
    unsigned long long d;
    asm("mov.b64 %0, {%1, %1};" : "=l"(d) : "f"(s));
    return d;
}
__device__ __forceinline__ void unpack2(unsigned long long v, float& lo, float& hi) {
    asm("mov.b64 {%0, %1}, %2;" : "=f"(lo), "=f"(hi) : "l"(v));
}

// ---------------------------------------------------------------------------
// Rearrange weights once per launch (tiny)
// ---------------------------------------------------------------------------
__global__ void rearrange_kernel(const float* __restrict__ offw,
                                 const float* __restrict__ w) {
    int i = blockIdx.x * blockDim.x + threadIdx.x;
    if (i < KK * CIN * OWPAD) {
        int c  = i % OWPAD;
        int t  = i / OWPAD;
        int ci = t % CIN;
        int k  = t / CIN;
        g_owr[i] = (c < COFF) ? offw[(c * CIN + ci) * KK + k] : 0.f;
    }
    if (i < KK * CIN * COUT) {
        int co = i % COUT;
        int t  = i / COUT;
        int ci = t % CIN;
        int k  = t / CIN;
        g_wr[i] = w[(co * CIN + ci) * KK + k];
    }
}

// ---------------------------------------------------------------------------
// Stage 1: dense offset conv.  lane = output position; 42 f32x2 accs/thread.
// ---------------------------------------------------------------------------
__global__ __launch_bounds__(128)
void offconv_kernel(const float* __restrict__ x, const float* __restrict__ ob) {
    __shared__ __align__(16) float ws[CIN * OWPAD];   // weights for current k (10.5 KB)

    int tid   = threadIdx.x;
    int gwarp = blockIdx.x * 4 + (tid >> 5);
    int lane  = tid & 31;
    int p     = gwarp * 32 + lane;                 // 50176 = 1568 warps exactly
    int zo    = p / (HH * WW);
    int r     = p - zo * (HH * WW);
    int yo    = r / WW;
    int xo    = r - yo * WW;

    unsigned long long acc2[OWPAD / 2];
#pragma unroll
    for (int c = 0; c < OWPAD / 2; c++) acc2[c] = 0ull;

    for (int k = 0; k < KK; k++) {
        __syncthreads();
        {   // stage weights for this k: 32*84 floats = 672 float4
            const float4* src = (const float4*)(g_owr + k * CIN * OWPAD);
            float4* dst = (float4*)ws;
            for (int i = tid; i < (CIN * OWPAD) / 4; i += 128) dst[i] = src[i];
        }
        __syncthreads();

        int kz = k / 9, ky = (k / 3) % 3, kx = k % 3;
        int zi = zo + kz - 1, yi = yo + ky - 1, xi = xo + kx - 1;
        bool valid = ((unsigned)zi < DD) & ((unsigned)yi < HH) & ((unsigned)xi < WW);
        int xidx = (zi * HH + yi) * WW + xi;

#pragma unroll 4
        for (int ci = 0; ci < CIN; ci++) {
            float xv = valid ? __ldg(x + ci * DHW + xidx) : 0.f;
            unsigned long long xv2 = pack2(xv);
            const ulonglong2* wv = (const ulonglong2*)(ws + ci * OWPAD);
#pragma unroll
            for (int j = 0; j < OWPAD / 4; j++) {     // 21 LDS.128 -> 42 fma2
                ulonglong2 w2 = wv[j];
                acc2[2*j+0] = fma2(xv2, w2.x, acc2[2*j+0]);
                acc2[2*j+1] = fma2(xv2, w2.y, acc2[2*j+1]);
            }
        }
    }

#pragma unroll
    for (int i = 0; i < OWPAD / 2; i++) {
        float lo, hi;
        unpack2(acc2[i], lo, hi);
        int c = 2 * i;
        if (c < COFF)     g_off[c * PP + p]       = lo + __ldg(ob + c);
        if (c + 1 < COFF) g_off[(c + 1) * PP + p] = hi + __ldg(ob + c + 1);
    }
}

// ---------------------------------------------------------------------------
// Stage 2: trilinear deformable sampling fused with the 64xCinK GEMM.
// lane = output position; 32 f32x2 accs/thread; weights broadcast from smem.
// ---------------------------------------------------------------------------
__global__ __launch_bounds__(128)
void deform_kernel(const float* __restrict__ x, const float* __restrict__ bias,
                   float* __restrict__ out) {
    __shared__ __align__(16) float ws[CIN * COUT];    // weights for current k (8 KB)

    int tid   = threadIdx.x;
    int gwarp = blockIdx.x * 4 + (tid >> 5);
    int lane  = tid & 31;
    int p     = gwarp * 32 + lane;
    int zo    = p / (HH * WW);
    int r     = p - zo * (HH * WW);
    int yo    = r / WW;
    int xo    = r - yo * WW;

    unsigned long long acc2[COUT / 2];
#pragma unroll
    for (int c = 0; c < COUT / 2; c++) acc2[c] = 0ull;

    for (int k = 0; k < KK; k++) {
        __syncthreads();
        {   // stage weights for this k: 2048 floats = 512 float4
            const float4* src = (const float4*)(g_wr + k * CIN * COUT);
            float4* dst = (float4*)ws;
            for (int i = tid; i < (CIN * COUT) / 4; i += 128) dst[i] = src[i];
        }
        __syncthreads();

        int kz = k / 9, ky = (k / 3) % 3, kx = k % 3;
        float dz = g_off[(3*k+0) * PP + p];
        float dy = g_off[(3*k+1) * PP + p];
        float dx = g_off[(3*k+2) * PP + p];
        float zc = (float)(zo + kz - 1) + dz;
        float yc = (float)(yo + ky - 1) + dy;
        float xc = (float)(xo + kx - 1) + dx;
        float z0f = floorf(zc), y0f = floorf(yc), x0f = floorf(xc);
        float fz = zc - z0f, fy = yc - y0f, fx = xc - x0f;
        int z0 = (int)z0f, y0 = (int)y0f, x0 = (int)x0f;

        float w8[8];
        int   id8[8];
#pragma unroll
        for (int j = 0; j < 8; j++) {
            int dzc = (j >> 2) & 1, dyc = (j >> 1) & 1, dxc = j & 1;
            int zi = z0 + dzc, yi = y0 + dyc, xi = x0 + dxc;
            bool v = ((unsigned)zi < DD) & ((unsigned)yi < HH) & ((unsigned)xi < WW);
            float wz = dzc ? fz : 1.f - fz;
            float wy = dyc ? fy : 1.f - fy;
            float wx = dxc ? fx : 1.f - fx;
            float wt = wz * wy * wx;
            w8[j] = v ? wt : 0.f;
            int zic = min(max(zi, 0), DD - 1);
            int yic = min(max(yi, 0), HH - 1);
            int xic = min(max(xi, 0), WW - 1);
            id8[j] = (zic * HH + yic) * WW + xic;
        }

#pragma unroll 4
        for (int ci = 0; ci < CIN; ci++) {
            const float* xp = x + ci * DHW;
            float s = 0.f;
#pragma unroll
            for (int j = 0; j < 8; j++) s += w8[j] * __ldg(xp + id8[j]);
            unsigned long long s2 = pack2(s);
            const ulonglong2* wv = (const ulonglong2*)(ws + ci * COUT);
#pragma unroll
            for (int j = 0; j < COUT / 4; j++) {      // 16 LDS.128 -> 32 fma2
                ulonglong2 w2 = wv[j];
                acc2[2*j+0] = fma2(s2, w2.x, acc2[2*j+0]);
                acc2[2*j+1] = fma2(s2, w2.y, acc2[2*j+1]);
            }
        }
    }

#pragma unroll
    for (int i = 0; i < COUT / 2; i++) {
        float lo, hi;
        unpack2(acc2[i], lo, hi);
        out[(2*i+0) * PP + p] = lo + __ldg(bias + 2*i+0);
        out[(2*i+1) * PP + p] = hi + __ldg(bias + 2*i+1);
    }
}

// ---------------------------------------------------------------------------
extern "C" void kernel_launch(void* const* d_in, const int* in_sizes, int n_in,
                              void* d_out, int out_size) {
    const float* x    = (const float*)d_in[0];  // [32,16,56,56]
    const float* offw = (const float*)d_in[1];  // [81,32,3,3,3]
    const float* offb = (const float*)d_in[2];  // [81]
    const float* w    = (const float*)d_in[3];  // [64,32,3,3,3]
    const float* b    = (const float*)d_in[4];  // [64]
    float* out = (float*)d_out;                 // [64,16,56,56]

    rearrange_kernel<<<(KK * CIN * OWPAD + 255) / 256, 256>>>(offw, w);
    offconv_kernel<<<392, 128>>>(x, offb);      // 392 blocks * 4 warps * 32 = 50176
    deform_kernel<<<392, 128>>>(x, b, out);
}